// round 5
// baseline (speedup 1.0000x reference)
#include <cuda_runtime.h>
#include <math.h>

// Problem dims (fixed by the reference)
#define BATCH 16
#define NQ    500   // queries (pred)
#define NT    128   // targets
#define KPT   34    // 17 keypoints * 2

// Transposed cost scratch: [b][target n][query q], float32 (exactly the values
// the reference casts to float64 before LSA).
__device__ float g_ct[BATCH * NT * NQ];

// ---------------------------------------------------------------------------
// Kernel 1: cost matrix. One block per (b, q), 128 threads = one per target n.
// Writes C[b][q][n] to d_out and the transposed copy to g_ct.
// ---------------------------------------------------------------------------
__global__ __launch_bounds__(128) void cost_kernel(
    const float* __restrict__ pred_boxes,   // (B, Q, 4)  cxcywh
    const float* __restrict__ pred_kpts,    // (B, Q, 17, 2)
    const float* __restrict__ tgt_boxes,    // (B, N, 4)  cxcywh
    const float* __restrict__ tgt_kpts,     // (B, N, 17, 2)
    float* __restrict__ C)                  // (B, Q, N)
{
    const int q = blockIdx.x;
    const int b = blockIdx.y;
    const int n = threadIdx.x;

    __shared__ float s_pk[KPT];
    __shared__ float s_pb[4];
    const float* pbq = pred_boxes + (b * NQ + q) * 4;
    const float* pkq = pred_kpts + (size_t)(b * NQ + q) * KPT;
    if (n < KPT) s_pk[n] = pkq[n];
    if (n < 4)   s_pb[n] = pbq[n];
    __syncthreads();

    const float* tbn = tgt_boxes + (b * NT + n) * 4;
    const float* tkn = tgt_kpts + (size_t)(b * NT + n) * KPT;

    const float p0 = s_pb[0], p1 = s_pb[1], p2 = s_pb[2], p3 = s_pb[3];
    const float t0 = tbn[0], t1 = tbn[1], t2 = tbn[2], t3 = tbn[3];

    // L1 bbox cost
    float cbbox = fabsf(p0 - t0) + fabsf(p1 - t1) + fabsf(p2 - t2) + fabsf(p3 - t3);

    // cxcywh -> xyxy with degenerate clamp (EPS_WH = 1e-4)
    float px0 = p0 - 0.5f * p2, py0 = p1 - 0.5f * p3;
    float px1 = p0 + 0.5f * p2, py1 = p1 + 0.5f * p3;
    px1 = fmaxf(px1, px0 + 1e-4f);
    py1 = fmaxf(py1, py0 + 1e-4f);
    float tx0 = t0 - 0.5f * t2, ty0 = t1 - 0.5f * t3;
    float tx1 = t0 + 0.5f * t2, ty1 = t1 + 0.5f * t3;
    tx1 = fmaxf(tx1, tx0 + 1e-4f);
    ty1 = fmaxf(ty1, ty0 + 1e-4f);

    const float ap = (px1 - px0) * (py1 - py0);
    const float at = (tx1 - tx0) * (ty1 - ty0);

    const float iw = fmaxf(fminf(px1, tx1) - fmaxf(px0, tx0), 0.0f);
    const float ih = fmaxf(fminf(py1, ty1) - fmaxf(py0, ty0), 0.0f);
    const float inter = iw * ih;
    const float uni = ap + at - inter;
    const float iou = inter / uni;

    const float ew = fmaxf(fmaxf(px1, tx1) - fminf(px0, tx0), 0.0f);
    const float eh = fmaxf(fmaxf(py1, ty1) - fminf(py0, ty0), 0.0f);
    const float enc = ew * eh;
    const float giou = iou - (enc - uni) / enc;

    float ckpt = 0.0f;
#pragma unroll
    for (int k = 0; k < KPT; k++) ckpt += fabsf(s_pk[k] - tkn[k]);

    const float cost = 5.0f * cbbox - 2.0f * giou + 1.0f * ckpt;

    C[(size_t)(b * NQ + q) * NT + n] = cost;
    g_ct[(size_t)(b * NT + n) * NQ + q] = cost;  // transposed for LSA row access
}

// ---------------------------------------------------------------------------
// Kernel 2: exact JV (shortest augmenting path) LSA on the (NT x NQ) transposed
// cost, float64 arithmetic, mirroring the reference's _lsa() exactly
// (including the first-occurrence / smallest-index argmin tie-break).
// One block per batch, 128 threads.
// ---------------------------------------------------------------------------
__global__ __launch_bounds__(128) void lsa_kernel(float* __restrict__ out, int out_size)
{
    const int b   = blockIdx.x;
    const int tid = threadIdx.x;
    const float* __restrict__ ct = g_ct + (size_t)b * NT * NQ;

    __shared__ double v[NQ];
    __shared__ double spc[NQ];
    __shared__ double u[NT];
    __shared__ int    path[NQ];
    __shared__ int    row4col[NQ];
    __shared__ int    col4row[NT];
    __shared__ unsigned char SC[NQ];
    __shared__ unsigned char SR[NT];
    __shared__ double s_minval;
    __shared__ int    s_i, s_sink;
    __shared__ double s_wv[4];
    __shared__ int    s_wj[4];

    const double DINF = __longlong_as_double(0x7FF0000000000000LL);

    // global init
    u[tid] = 0.0;
    col4row[tid] = -1;
    for (int j = tid; j < NQ; j += 128) { v[j] = 0.0; row4col[j] = -1; }
    __syncthreads();

    for (int cur = 0; cur < NT; cur++) {
        // phase init
        for (int j = tid; j < NQ; j += 128) { spc[j] = DINF; path[j] = -1; SC[j] = 0; }
        SR[tid] = 0;
        if (tid == 0) { s_i = cur; s_minval = 0.0; s_sink = -1; }
        __syncthreads();

        // shortest augmenting path
        while (true) {
            if (s_sink >= 0) break;
            const int    i    = s_i;
            const double minv = s_minval;
            if (tid == 0) SR[i] = 1;
            const double u_i = u[i];
            const float* __restrict__ crow = ct + (size_t)i * NQ;

            // update shortest-path costs over columns not in SC; fused local argmin
            double lmin = DINF;
            int    lj   = NQ;
            for (int j = tid; j < NQ; j += 128) {
                if (!SC[j]) {
                    const double r = minv + (double)__ldg(crow + j) - u_i - v[j];
                    if (r < spc[j]) { spc[j] = r; path[j] = i; }
                    const double s = spc[j];
                    if (s < lmin) { lmin = s; lj = j; }  // ascending j -> first-min kept
                }
            }

            // warp argmin (tie -> smaller j, matching numpy argmin semantics)
            for (int off = 16; off > 0; off >>= 1) {
                const double ov = __shfl_down_sync(0xffffffffu, lmin, off);
                const int    oj = __shfl_down_sync(0xffffffffu, lj, off);
                if (ov < lmin || (ov == lmin && oj < lj)) { lmin = ov; lj = oj; }
            }
            if ((tid & 31) == 0) { s_wv[tid >> 5] = lmin; s_wj[tid >> 5] = lj; }
            __syncthreads();

            if (tid == 0) {
                double bm = s_wv[0];
                int    bj = s_wj[0];
#pragma unroll
                for (int w = 1; w < 4; w++)
                    if (s_wv[w] < bm || (s_wv[w] == bm && s_wj[w] < bj)) { bm = s_wv[w]; bj = s_wj[w]; }
                s_minval = bm;
                SC[bj] = 1;
                const int r4c = row4col[bj];
                if (r4c < 0) s_sink = bj;
                else         s_i = r4c;
            }
            __syncthreads();
        }

        // dual updates (pre-augmentation state, exactly as the reference)
        const double minv = s_minval;
        if (tid == cur)      u[tid] += minv;
        else if (SR[tid])    u[tid] += minv - spc[col4row[tid]];
        for (int j = tid; j < NQ; j += 128)
            if (SC[j]) v[j] -= minv - spc[j];
        __syncthreads();

        // augment along the alternating path (sequential, thread 0)
        if (tid == 0) {
            int j = s_sink;
            while (true) {
                const int i = path[j];
                row4col[j] = i;
                const int nj = col4row[i];
                col4row[i] = j;
                j = nj;
                if (i == cur) break;
            }
        }
        __syncthreads();
    }

    // Emit row_ind / col_ind in the reference's sorted-by-query order.
    // col4row[t] = query assigned to target t; values are distinct, so the
    // rank of col4row[t] among all 128 values is its output position.
    if (out_size >= BATCH * NQ * NT + 2 * BATCH * NT) {
        const int q = col4row[tid];
        int rank = 0;
#pragma unroll 8
        for (int t = 0; t < NT; t++) rank += (col4row[t] < q) ? 1 : 0;
        float* rows = out + (size_t)BATCH * NQ * NT;
        float* cols = rows + BATCH * NT;
        rows[b * NT + rank] = (float)q;    // row_ind: sorted query indices
        cols[b * NT + rank] = (float)tid;  // col_ind: target index for that query
    }
}

// ---------------------------------------------------------------------------
extern "C" void kernel_launch(void* const* d_in, const int* in_sizes, int n_in,
                              void* d_out, int out_size)
{
    const float* pred_boxes = (const float*)d_in[0];   // (16, 500, 4)
    const float* pred_kpts  = (const float*)d_in[1];   // (16, 500, 17, 2)
    const float* tgt_boxes  = (const float*)d_in[2];   // (16, 128, 4)
    const float* tgt_kpts   = (const float*)d_in[3];   // (16, 128, 17, 2)
    float* out = (float*)d_out;

    dim3 grid(NQ, BATCH);
    cost_kernel<<<grid, 128>>>(pred_boxes, pred_kpts, tgt_boxes, tgt_kpts, out);
    lsa_kernel<<<BATCH, 128>>>(out, out_size);
}

// round 6
// speedup vs baseline: 1.6951x; 1.6951x over previous
#include <cuda_runtime.h>
#include <math.h>

// Problem dims (fixed by the reference)
#define BATCH 16
#define NQ    500   // queries (pred)
#define NT    128   // targets
#define KPT   34    // 17 keypoints * 2

// Transposed cost scratch: [b][target n][query q]
__device__ float  g_ct [BATCH * NT * NQ];   // f32 (for exact row reduction)
__device__ double g_dct[BATCH * NT * NQ];   // f64 (for Dijkstra inner loop)

// ---------------------------------------------------------------------------
// Kernel 1: cost matrix. One block per (b, q), 128 threads = one per target n.
// ---------------------------------------------------------------------------
__global__ __launch_bounds__(128) void cost_kernel(
    const float* __restrict__ pred_boxes,   // (B, Q, 4)  cxcywh
    const float* __restrict__ pred_kpts,    // (B, Q, 17, 2)
    const float* __restrict__ tgt_boxes,    // (B, N, 4)  cxcywh
    const float* __restrict__ tgt_kpts,     // (B, N, 17, 2)
    float* __restrict__ C)                  // (B, Q, N)
{
    const int q = blockIdx.x;
    const int b = blockIdx.y;
    const int n = threadIdx.x;

    __shared__ float s_pk[KPT];
    __shared__ float s_pb[4];
    const float* pbq = pred_boxes + (b * NQ + q) * 4;
    const float* pkq = pred_kpts + (size_t)(b * NQ + q) * KPT;
    if (n < KPT) s_pk[n] = pkq[n];
    if (n < 4)   s_pb[n] = pbq[n];
    __syncthreads();

    const float* tbn = tgt_boxes + (b * NT + n) * 4;
    const float* tkn = tgt_kpts + (size_t)(b * NT + n) * KPT;

    const float p0 = s_pb[0], p1 = s_pb[1], p2 = s_pb[2], p3 = s_pb[3];
    const float t0 = tbn[0], t1 = tbn[1], t2 = tbn[2], t3 = tbn[3];

    float cbbox = fabsf(p0 - t0) + fabsf(p1 - t1) + fabsf(p2 - t2) + fabsf(p3 - t3);

    float px0 = p0 - 0.5f * p2, py0 = p1 - 0.5f * p3;
    float px1 = p0 + 0.5f * p2, py1 = p1 + 0.5f * p3;
    px1 = fmaxf(px1, px0 + 1e-4f);
    py1 = fmaxf(py1, py0 + 1e-4f);
    float tx0 = t0 - 0.5f * t2, ty0 = t1 - 0.5f * t3;
    float tx1 = t0 + 0.5f * t2, ty1 = t1 + 0.5f * t3;
    tx1 = fmaxf(tx1, tx0 + 1e-4f);
    ty1 = fmaxf(ty1, ty0 + 1e-4f);

    const float ap = (px1 - px0) * (py1 - py0);
    const float at = (tx1 - tx0) * (ty1 - ty0);

    const float iw = fmaxf(fminf(px1, tx1) - fmaxf(px0, tx0), 0.0f);
    const float ih = fmaxf(fminf(py1, ty1) - fmaxf(py0, ty0), 0.0f);
    const float inter = iw * ih;
    const float uni = ap + at - inter;
    const float iou = inter / uni;

    const float ew = fmaxf(fmaxf(px1, tx1) - fminf(px0, tx0), 0.0f);
    const float eh = fmaxf(fmaxf(py1, ty1) - fminf(py0, ty0), 0.0f);
    const float enc = ew * eh;
    const float giou = iou - (enc - uni) / enc;

    float ckpt = 0.0f;
#pragma unroll
    for (int k = 0; k < KPT; k++) ckpt += fabsf(s_pk[k] - tkn[k]);

    const float cost = 5.0f * cbbox - 2.0f * giou + 1.0f * ckpt;

    C[(size_t)(b * NQ + q) * NT + n] = cost;
    const size_t ti = (size_t)(b * NT + n) * NQ + q;
    g_ct[ti]  = cost;
    g_dct[ti] = (double)cost;
}

// ---------------------------------------------------------------------------
// Kernel 2: exact JV LSA with row-reduction + greedy init (dual-feasible, so
// the optimum is exact and — being unique for continuous random costs —
// identical to the reference's plain shortest-augmenting-path result).
// One block per batch, 128 threads, f64 arithmetic throughout the path search.
// ---------------------------------------------------------------------------
__global__ __launch_bounds__(128) void lsa_kernel(float* __restrict__ out, int out_size)
{
    const int b    = blockIdx.x;
    const int tid  = threadIdx.x;
    const int lane = tid & 31;
    const int wid  = tid >> 5;
    const float*  __restrict__ ct  = g_ct  + (size_t)b * NT * NQ;
    const double* __restrict__ dct = g_dct + (size_t)b * NT * NQ;

    __shared__ double v[NQ];
    __shared__ double spc[NQ];
    __shared__ double u[NT];
    __shared__ int    path[NQ];
    __shared__ int    row4col[NQ];
    __shared__ int    col4row[NT];
    __shared__ int    jmin[NT];
    __shared__ unsigned char SC[NQ];
    __shared__ unsigned char SR[NT];
    __shared__ double s_minval;
    __shared__ int    s_i, s_sink;
    __shared__ double s_wv[4];
    __shared__ int    s_wj[4];

    const double DINF = __longlong_as_double(0x7FF0000000000000LL);
    const float  FINF = __int_as_float(0x7F800000);

    // ---- global init ----
    col4row[tid] = -1;
    SR[tid] = 0;
    for (int j = tid; j < NQ; j += 128) { v[j] = 0.0; row4col[j] = -1; }
    __syncthreads();

    // ---- row reduction: u[i] = min_j c[i][j] (exact in f32), record argmin ----
    // warp w handles rows w, w+4, ...; lanes stride the 500 columns (coalesced).
    for (int r = wid; r < NT; r += 4) {
        const float* __restrict__ row = ct + (size_t)r * NQ;
        float m = FINF; int mj = NQ;
        for (int j = lane; j < NQ; j += 32) {
            const float c = __ldg(row + j);
            if (c < m) { m = c; mj = j; }   // ascending j -> first-min kept
        }
#pragma unroll
        for (int off = 16; off > 0; off >>= 1) {
            const float ov = __shfl_down_sync(0xffffffffu, m, off);
            const int   oj = __shfl_down_sync(0xffffffffu, mj, off);
            if (ov < m || (ov == m && oj < mj)) { m = ov; mj = oj; }
        }
        if (lane == 0) { u[r] = (double)m; jmin[r] = mj; }
    }
    __syncthreads();

    // ---- greedy zero-assignment (thread 0, 128 serial steps) ----
    if (tid == 0) {
        for (int i = 0; i < NT; i++) {
            const int j = jmin[i];
            if (row4col[j] < 0) { row4col[j] = i; col4row[i] = j; }
        }
    }
    __syncthreads();

    // ---- augmenting phases for the remaining free rows ----
    for (int cur = 0; cur < NT; cur++) {
        if (col4row[cur] >= 0) continue;   // shared, uniform across block

        for (int j = tid; j < NQ; j += 128) { spc[j] = DINF; path[j] = -1; SC[j] = 0; }
        SR[tid] = 0;
        if (tid == 0) { s_i = cur; s_minval = 0.0; s_sink = -1; }
        __syncthreads();

        while (true) {
            if (s_sink >= 0) break;
            const int    i    = s_i;
            const double minv = s_minval;
            if (tid == 0) SR[i] = 1;
            const double w = minv - u[i];
            const double* __restrict__ drow = dct + (size_t)i * NQ;

            // spc update (safe to skip SC test: r >= minv >= spc[settled],
            // strict '<' never fires on settled columns) + fused local argmin
            double lmin = DINF;
            int    lj   = NQ;
            for (int j = tid; j < NQ; j += 128) {
                double sj = spc[j];
                const double r = (__ldg(drow + j) + w) - v[j];
                if (r < sj) { spc[j] = r; path[j] = i; sj = r; }
                const double cand = SC[j] ? DINF : sj;
                if (cand < lmin) { lmin = cand; lj = j; }
            }

            // warp argmin (tie -> smaller j)
#pragma unroll
            for (int off = 16; off > 0; off >>= 1) {
                const double ov = __shfl_down_sync(0xffffffffu, lmin, off);
                const int    oj = __shfl_down_sync(0xffffffffu, lj, off);
                if (ov < lmin || (ov == lmin && oj < lj)) { lmin = ov; lj = oj; }
            }
            if (lane == 0) { s_wv[wid] = lmin; s_wj[wid] = lj; }
            __syncthreads();

            if (tid == 0) {
                double bm = s_wv[0];
                int    bj = s_wj[0];
#pragma unroll
                for (int wv = 1; wv < 4; wv++)
                    if (s_wv[wv] < bm || (s_wv[wv] == bm && s_wj[wv] < bj)) { bm = s_wv[wv]; bj = s_wj[wv]; }
                s_minval = bm;
                SC[bj] = 1;
                const int r4c = row4col[bj];
                if (r4c < 0) s_sink = bj;
                else         s_i = r4c;
            }
            __syncthreads();
        }

        // dual updates (pre-augmentation state, exactly the JV formulas)
        const double minv = s_minval;
        if (tid == cur)      u[tid] += minv;
        else if (SR[tid])    u[tid] += minv - spc[col4row[tid]];
        for (int j = tid; j < NQ; j += 128)
            if (SC[j]) v[j] -= minv - spc[j];
        __syncthreads();

        // augment along the alternating path (thread 0)
        if (tid == 0) {
            int j = s_sink;
            while (true) {
                const int i = path[j];
                row4col[j] = i;
                const int nj = col4row[i];
                col4row[i] = j;
                j = nj;
                if (i == cur) break;
            }
        }
        __syncthreads();
    }

    // ---- emit row_ind / col_ind in the reference's sorted-by-query order ----
    if (out_size >= BATCH * NQ * NT + 2 * BATCH * NT) {
        const int q = col4row[tid];
        int rank = 0;
#pragma unroll 8
        for (int t = 0; t < NT; t++) rank += (col4row[t] < q) ? 1 : 0;
        float* rows = out + (size_t)BATCH * NQ * NT;
        float* cols = rows + BATCH * NT;
        rows[b * NT + rank] = (float)q;    // row_ind: sorted query indices
        cols[b * NT + rank] = (float)tid;  // col_ind: target index for that query
    }
}

// ---------------------------------------------------------------------------
extern "C" void kernel_launch(void* const* d_in, const int* in_sizes, int n_in,
                              void* d_out, int out_size)
{
    const float* pred_boxes = (const float*)d_in[0];   // (16, 500, 4)
    const float* pred_kpts  = (const float*)d_in[1];   // (16, 500, 17, 2)
    const float* tgt_boxes  = (const float*)d_in[2];   // (16, 128, 4)
    const float* tgt_kpts   = (const float*)d_in[3];   // (16, 128, 17, 2)
    float* out = (float*)d_out;

    dim3 grid(NQ, BATCH);
    cost_kernel<<<grid, 128>>>(pred_boxes, pred_kpts, tgt_boxes, tgt_kpts, out);
    lsa_kernel<<<BATCH, 128>>>(out, out_size);
}

// round 7
// speedup vs baseline: 1.8756x; 1.1065x over previous
#include <cuda_runtime.h>
#include <math.h>

// Problem dims (fixed by the reference)
#define BATCH 16
#define NQ    500   // queries (pred) = columns
#define NT    128   // targets       = rows
#define KPT   34    // 17 keypoints * 2
#define NCPL  16    // columns per lane: ceil(500/32)

// Transposed cost scratch: [b][target n][query q]
__device__ float  g_ct [BATCH * NT * NQ];   // f32 (exact row reduction)
__device__ double g_dct[BATCH * NT * NQ];   // f64 (path search)

// ---------------------------------------------------------------------------
// Kernel 1: cost matrix. One block per (b, q), 128 threads = one per target n.
// ---------------------------------------------------------------------------
__global__ __launch_bounds__(128) void cost_kernel(
    const float* __restrict__ pred_boxes,   // (B, Q, 4)  cxcywh
    const float* __restrict__ pred_kpts,    // (B, Q, 17, 2)
    const float* __restrict__ tgt_boxes,    // (B, N, 4)  cxcywh
    const float* __restrict__ tgt_kpts,     // (B, N, 17, 2)
    float* __restrict__ C)                  // (B, Q, N)
{
    const int q = blockIdx.x;
    const int b = blockIdx.y;
    const int n = threadIdx.x;

    __shared__ float s_pk[KPT];
    __shared__ float s_pb[4];
    const float* pbq = pred_boxes + (b * NQ + q) * 4;
    const float* pkq = pred_kpts + (size_t)(b * NQ + q) * KPT;
    if (n < KPT) s_pk[n] = pkq[n];
    if (n < 4)   s_pb[n] = pbq[n];
    __syncthreads();

    const float* tbn = tgt_boxes + (b * NT + n) * 4;
    const float* tkn = tgt_kpts + (size_t)(b * NT + n) * KPT;

    const float p0 = s_pb[0], p1 = s_pb[1], p2 = s_pb[2], p3 = s_pb[3];
    const float t0 = tbn[0], t1 = tbn[1], t2 = tbn[2], t3 = tbn[3];

    float cbbox = fabsf(p0 - t0) + fabsf(p1 - t1) + fabsf(p2 - t2) + fabsf(p3 - t3);

    float px0 = p0 - 0.5f * p2, py0 = p1 - 0.5f * p3;
    float px1 = p0 + 0.5f * p2, py1 = p1 + 0.5f * p3;
    px1 = fmaxf(px1, px0 + 1e-4f);
    py1 = fmaxf(py1, py0 + 1e-4f);
    float tx0 = t0 - 0.5f * t2, ty0 = t1 - 0.5f * t3;
    float tx1 = t0 + 0.5f * t2, ty1 = t1 + 0.5f * t3;
    tx1 = fmaxf(tx1, tx0 + 1e-4f);
    ty1 = fmaxf(ty1, ty0 + 1e-4f);

    const float ap = (px1 - px0) * (py1 - py0);
    const float at = (tx1 - tx0) * (ty1 - ty0);

    const float iw = fmaxf(fminf(px1, tx1) - fmaxf(px0, tx0), 0.0f);
    const float ih = fmaxf(fminf(py1, ty1) - fmaxf(py0, ty0), 0.0f);
    const float inter = iw * ih;
    const float uni = ap + at - inter;
    const float iou = inter / uni;

    const float ew = fmaxf(fmaxf(px1, tx1) - fminf(px0, tx0), 0.0f);
    const float eh = fmaxf(fmaxf(py1, ty1) - fminf(py0, ty0), 0.0f);
    const float enc = ew * eh;
    const float giou = iou - (enc - uni) / enc;

    float ckpt = 0.0f;
#pragma unroll
    for (int k = 0; k < KPT; k++) ckpt += fabsf(s_pk[k] - tkn[k]);

    const float cost = 5.0f * cbbox - 2.0f * giou + 1.0f * ckpt;

    C[(size_t)(b * NQ + q) * NT + n] = cost;
    const size_t ti = (size_t)(b * NT + n) * NQ + q;
    g_ct[ti]  = cost;
    g_dct[ti] = (double)cost;
}

// Monotone bijection double -> uint64 (order-preserving for all finite/inf).
__device__ __forceinline__ unsigned long long dkey(double x) {
    long long b = __double_as_longlong(x);
    return (unsigned long long)b ^ ((b < 0) ? 0xFFFFFFFFFFFFFFFFULL
                                             : 0x8000000000000000ULL);
}

// ---------------------------------------------------------------------------
// Kernel 2: exact JV LSA. Init: row reduction + greedy + LAPJV augmenting
// row reduction (every step maintains dual feasibility + complementary
// slackness, so the Dijkstra phases yield the exact optimum, which is unique
// for continuous random costs -> matches the reference's result).
// One block per batch; init uses 4 warps, main loop is single-warp (no
// __syncthreads, integer-key argmin reductions).
// ---------------------------------------------------------------------------
__global__ __launch_bounds__(128) void lsa_kernel(float* __restrict__ out, int out_size)
{
    const int b    = blockIdx.x;
    const int tid  = threadIdx.x;
    const int lane = tid & 31;
    const int wid  = tid >> 5;
    const float*  __restrict__ ct  = g_ct  + (size_t)b * NT * NQ;
    const double* __restrict__ dct = g_dct + (size_t)b * NT * NQ;

    __shared__ double v[NQ];
    __shared__ double spc[NQ];
    __shared__ double u[NT];
    __shared__ int    path[NQ];
    __shared__ int    row4col[NQ];
    __shared__ int    col4row[NT];
    __shared__ int    jmin[NT];
    __shared__ int    freelist[NT];
    __shared__ unsigned char SC[NQ];
    __shared__ unsigned char SR[NT];
    __shared__ int    s_nf;

    const double DINF = __longlong_as_double(0x7FF0000000000000LL);
    const float  FINF = __int_as_float(0x7F800000);
    const unsigned FULL = 0xffffffffu;

    // ---- global init (all 128 threads) ----
    col4row[tid] = -1;
    for (int j = tid; j < NQ; j += 128) { v[j] = 0.0; row4col[j] = -1; }
    __syncthreads();

    // ---- row reduction: u[i] = min_j c[i][j] (exact in f32) ----
    for (int r = wid; r < NT; r += 4) {
        const float* __restrict__ row = ct + (size_t)r * NQ;
        float m = FINF; int mj = 0;
        for (int j = lane; j < NQ; j += 32) {
            const float c = __ldg(row + j);
            if (c < m) { m = c; mj = j; }
        }
#pragma unroll
        for (int off = 16; off > 0; off >>= 1) {
            const float ov = __shfl_down_sync(FULL, m, off);
            const int   oj = __shfl_down_sync(FULL, mj, off);
            if (ov < m || (ov == m && oj < mj)) { m = ov; mj = oj; }
        }
        if (lane == 0) { u[r] = (double)m; jmin[r] = mj; }
    }
    __syncthreads();

    // ---- greedy zero-assignment + free-row list (thread 0) ----
    if (tid == 0) {
        int nf = 0;
        for (int i = 0; i < NT; i++) {
            const int j = jmin[i];
            if (row4col[j] < 0) { row4col[j] = i; col4row[i] = j; }
            else freelist[nf++] = i;
        }
        s_nf = nf;
    }
    __syncthreads();

    if (wid != 0) return;   // warp 0 carries on alone; no __syncthreads below

    // ======== LAPJV augmenting row reduction (warp-cooperative) ========
    {
        const int nf = s_nf;
        int li = 1;
        int i = (nf > 0) ? freelist[0] : -1;
        int steps = 0;
        const int cap = 4 * nf + 8;
        while (i >= 0 && steps < cap) {
            steps++;
            const double* __restrict__ drow = dct + (size_t)i * NQ;
            // per-lane min & second-min of rc = c[i][j] - v[j]
            double m1 = DINF, m2 = DINF;
            int j1 = -1, j2 = -1;
#pragma unroll
            for (int k = 0; k < NCPL; k++) {
                const int j = (k << 5) + lane;
                if (j < NQ) {
                    const double rc = __ldg(drow + j) - v[j];
                    if (rc < m1)      { m2 = m1; j2 = j1; m1 = rc; j1 = j; }
                    else if (rc < m2) { m2 = rc; j2 = j; }
                }
            }
#pragma unroll
            for (int off = 16; off > 0; off >>= 1) {
                const double om1 = __shfl_down_sync(FULL, m1, off);
                const double om2 = __shfl_down_sync(FULL, m2, off);
                const int    oj1 = __shfl_down_sync(FULL, j1, off);
                const int    oj2 = __shfl_down_sync(FULL, j2, off);
                if (om1 < m1) {
                    if (m1 < om2) { m2 = m1;  j2 = j1;  }
                    else          { m2 = om2; j2 = oj2; }
                    m1 = om1; j1 = oj1;
                } else if (om1 < m2) { m2 = om1; j2 = oj1; }
            }
            int nexti = -1;
            if (lane == 0) {
                const double u1 = m1, u2 = m2;
                int jj = j1;
                u[i] = u2;
                if (u1 < u2)                            v[jj] -= (u2 - u1);
                else if (row4col[jj] >= 0 && j2 >= 0)   jj = j2;   // u1 == u2
                const int kk = row4col[jj];
                row4col[jj] = i; col4row[i] = jj;
                if (kk >= 0) { col4row[kk] = -1; nexti = kk; }
                else         { nexti = (li < nf) ? freelist[li++] : -1; }
            }
            nexti = __shfl_sync(FULL, nexti, 0);
            i = nexti;
            __syncwarp();
        }
    }

    // ======== Dijkstra augmenting phases (single warp) ========
    for (int cur = 0; cur < NT; cur++) {
        if (col4row[cur] >= 0) continue;

        for (int j = lane; j < NQ; j += 32) { spc[j] = DINF; path[j] = -1; SC[j] = 0; }
        for (int r = lane; r < NT; r += 32) SR[r] = 0;
        __syncwarp();

        int i = cur, sink = -1;
        double minv = 0.0;
        while (sink < 0) {
            if (lane == 0) SR[i] = 1;
            const double w = minv - u[i];
            const double* __restrict__ drow = dct + (size_t)i * NQ;

            unsigned long long bk0 = ~0ULL, bk1 = ~0ULL, bk2 = ~0ULL, bk3 = ~0ULL;
            int bj0 = NQ, bj1 = NQ, bj2 = NQ, bj3 = NQ;
#pragma unroll
            for (int k = 0; k < NCPL; k++) {
                const int j = (k << 5) + lane;
                if (j < NQ && !SC[j]) {
                    double sj = spc[j];
                    const double r = (__ldg(drow + j) + w) - v[j];
                    if (r < sj) { spc[j] = r; path[j] = i; sj = r; }
                    const unsigned long long key = dkey(sj);
                    switch (k & 3) {
                        case 0: if (key < bk0) { bk0 = key; bj0 = j; } break;
                        case 1: if (key < bk1) { bk1 = key; bj1 = j; } break;
                        case 2: if (key < bk2) { bk2 = key; bj2 = j; } break;
                        default:if (key < bk3) { bk3 = key; bj3 = j; } break;
                    }
                }
            }
            // merge 4 accumulators (tie -> smaller j; within each, first-min kept)
            unsigned long long K = bk0; int J = bj0;
            if (bk1 < K || (bk1 == K && bj1 < J)) { K = bk1; J = bj1; }
            if (bk2 < K || (bk2 == K && bj2 < J)) { K = bk2; J = bj2; }
            if (bk3 < K || (bk3 == K && bj3 < J)) { K = bk3; J = bj3; }
            // warp argmin on integer keys (exact order of f64 spc)
#pragma unroll
            for (int off = 16; off > 0; off >>= 1) {
                const unsigned long long oK = __shfl_down_sync(FULL, K, off);
                const int                oJ = __shfl_down_sync(FULL, J, off);
                if (oK < K || (oK == K && oJ < J)) { K = oK; J = oJ; }
            }
            J = __shfl_sync(FULL, J, 0);
            __syncwarp();                 // spc writes visible before cross-lane read
            minv = spc[J];                // broadcast LDS (same address)
            const int r4c = row4col[J];
            if (lane == 0) SC[J] = 1;
            if (r4c < 0) sink = J; else i = r4c;
            __syncwarp();                 // SC write visible before next sweep
        }

        // dual updates (pre-augmentation state, exact JV formulas)
        for (int r = lane; r < NT; r += 32) {
            if (r == cur)     u[r] += minv;
            else if (SR[r])   u[r] += minv - spc[col4row[r]];
        }
        for (int j = lane; j < NQ; j += 32)
            if (SC[j]) v[j] -= minv - spc[j];
        __syncwarp();

        // augment along the alternating path (lane 0)
        if (lane == 0) {
            int j = sink;
            while (true) {
                const int ii = path[j];
                row4col[j] = ii;
                const int nj = col4row[ii];
                col4row[ii] = j;
                j = nj;
                if (ii == cur) break;
            }
        }
        __syncwarp();
    }

    // ---- emit row_ind / col_ind in sorted-by-query order ----
    if (out_size >= BATCH * NQ * NT + 2 * BATCH * NT) {
        float* rows = out + (size_t)BATCH * NQ * NT;
        float* cols = rows + BATCH * NT;
        for (int t = lane; t < NT; t += 32) {
            const int q = col4row[t];
            int rank = 0;
#pragma unroll 8
            for (int tt = 0; tt < NT; tt++) rank += (col4row[tt] < q) ? 1 : 0;
            rows[b * NT + rank] = (float)q;    // row_ind: sorted query indices
            cols[b * NT + rank] = (float)t;    // col_ind: target for that query
        }
    }
}

// ---------------------------------------------------------------------------
extern "C" void kernel_launch(void* const* d_in, const int* in_sizes, int n_in,
                              void* d_out, int out_size)
{
    const float* pred_boxes = (const float*)d_in[0];   // (16, 500, 4)
    const float* pred_kpts  = (const float*)d_in[1];   // (16, 500, 17, 2)
    const float* tgt_boxes  = (const float*)d_in[2];   // (16, 128, 4)
    const float* tgt_kpts   = (const float*)d_in[3];   // (16, 128, 17, 2)
    float* out = (float*)d_out;

    dim3 grid(NQ, BATCH);
    cost_kernel<<<grid, 128>>>(pred_boxes, pred_kpts, tgt_boxes, tgt_kpts, out);
    lsa_kernel<<<BATCH, 128>>>(out, out_size);
}